// round 6
// baseline (speedup 1.0000x reference)
#include <cuda_runtime.h>

typedef unsigned long long u64;

#define Tt    512
#define FOUT  20
#define NBLK  128
// Block: 8 warps = 4 groups x 2 warps. Group owns 8 samples.
// lane = (ph, j): ph = lane>>4, j = lane&15. unit u = wsub*16 + j.
// Lane computes all 4 gates of unit u for samples s = 4*ph .. 4*ph+3 (scalars).
// f32x2 packs (gate-pair): (i,g) and (f,o). State z stored DUPLICATED (z,z) in smem.

// ---- shared layout (floats) ----
#define OW1   0                          // [34][32 u][4] gates ordered (i,g,f,o)
#define OW2   (OW1 + 34*128)             // [64][32][4]
#define OWO   (OW2 + 64*128)             // [32][20]
#define OB1   (OWO + 640)                // [32][4] (i,g,f,o)
#define OB2   (OB1 + 128)
#define OBO   (OB2 + 128)                // [20] pad 32
#define OZ1   (OBO + 32)
// per group: x dup [2buf][2row][20] + h1 dup [2buf][32 u][20]
#define Z1G   (80 + 2*32*20)             // 1360
#define OZ2   (OZ1 + 4*Z1G)
// per group: h2 dup [2buf][32][20] + h2 compact [2buf][32][8]
#define Z2G   (2*32*20 + 2*32*8)         // 1792
#define SMEM_FLOATS (OZ2 + 4*Z2G)
#define SMEM_BYTES  (SMEM_FLOATS * 4)

#define GBAR(id) asm volatile("bar.sync %0, %1;" :: "r"(id), "r"(64) : "memory")

__device__ __forceinline__ u64 pk(float lo, float hi) {
    u64 r; asm("mov.b64 %0, {%1, %2};" : "=l"(r) : "f"(lo), "f"(hi)); return r;
}
__device__ __forceinline__ void upk(u64 v, float& lo, float& hi) {
    asm("mov.b64 {%0, %1}, %2;" : "=f"(lo), "=f"(hi) : "l"(v));
}
__device__ __forceinline__ u64 fma2(u64 a, u64 b, u64 c) {
    u64 d; asm("fma.rn.f32x2 %0, %1, %2, %3;" : "=l"(d) : "l"(a), "l"(b), "l"(c)); return d;
}
__device__ __forceinline__ float sigmf(float x) {
    return __fdividef(1.f, 1.f + __expf(-x));
}

// Scalar LSTM epilogue for one sample. ig=(i,g) preacts packed, fo=(f,o).
__device__ __forceinline__ float lstm_epi_s(u64 ig, u64 fo, float& c) {
    float pi, pg, pf, po;
    upk(ig, pi, pg); upk(fo, pf, po);
    float i = sigmf(pi), f = sigmf(pf), o = sigmf(po);
    float g = fmaf(2.f, sigmf(2.f * pg), -1.f);     // tanh
    c = fmaf(f, c, i * g);
    float tc = fmaf(2.f, sigmf(2.f * c), -1.f);     // tanh
    return o * tc;
}

__global__ void __launch_bounds__(256, 1)
lstm_seq_kernel(const float* __restrict__ x,
                const float* __restrict__ Wih1, const float* __restrict__ Whh1,
                const float* __restrict__ bih1, const float* __restrict__ bhh1,
                const float* __restrict__ Wih2, const float* __restrict__ Whh2,
                const float* __restrict__ bih2, const float* __restrict__ bhh2,
                const float* __restrict__ Wout, const float* __restrict__ bout,
                float* __restrict__ out)
{
    extern __shared__ float sm[];
    const int tid = threadIdx.x;

    // ---- stage weights, gate order (i,g,f,o) = indices (0,2,1,3) ----
    for (int idx = tid; idx < 34 * 32; idx += 256) {
        int k = idx >> 5, uu = idx & 31;
        #pragma unroll
        for (int cc = 0; cc < 4; cc++) {
            int g = (cc == 0) ? 0 : (cc == 1) ? 2 : (cc == 2) ? 1 : 3;
            float v = (k < 2) ? Wih1[(g * 32 + uu) * 2 + k]
                              : Whh1[(g * 32 + uu) * 32 + (k - 2)];
            sm[OW1 + idx * 4 + cc] = v;
        }
    }
    for (int idx = tid; idx < 64 * 32; idx += 256) {
        int k = idx >> 5, uu = idx & 31;
        #pragma unroll
        for (int cc = 0; cc < 4; cc++) {
            int g = (cc == 0) ? 0 : (cc == 1) ? 2 : (cc == 2) ? 1 : 3;
            float v = (k < 32) ? Wih2[(g * 32 + uu) * 32 + k]
                               : Whh2[(g * 32 + uu) * 32 + (k - 32)];
            sm[OW2 + idx * 4 + cc] = v;
        }
    }
    for (int idx = tid; idx < 32 * 20; idx += 256) {
        int k = idx / 20, o = idx % 20;
        sm[OWO + idx] = Wout[o * 32 + k];
    }
    for (int idx = tid; idx < 32; idx += 256) {
        #pragma unroll
        for (int cc = 0; cc < 4; cc++) {
            int g = (cc == 0) ? 0 : (cc == 1) ? 2 : (cc == 2) ? 1 : 3;
            sm[OB1 + idx * 4 + cc] = bih1[g * 32 + idx] + bhh1[g * 32 + idx];
            sm[OB2 + idx * 4 + cc] = bih2[g * 32 + idx] + bhh2[g * 32 + idx];
        }
    }
    for (int idx = tid; idx < FOUT; idx += 256) sm[OBO + idx] = bout[idx];
    // zero all state buffers
    for (int idx = tid; idx < 4 * Z1G + 4 * Z2G; idx += 256) sm[OZ1 + idx] = 0.f;
    __syncthreads();

    const int w    = tid >> 5;
    const int lane = tid & 31;
    const int grp  = w >> 1;
    const int wsub = w & 1;
    const int j    = lane & 15;
    const int ph   = lane >> 4;
    const int u    = wsub * 16 + j;
    const int sBase = blockIdx.x * 32 + grp * 8;
    const int bid  = grp + 1;              // named barrier id 1..4

    float* z1x  = sm + OZ1 + grp * Z1G;    // [2buf][2row][20] dup
    float* z1h  = z1x + 80;                // [2buf][32][20]   dup
    float* z2h2 = sm + OZ2 + grp * Z2G;    // [2buf][32][20]   dup
    float* h2c  = z2h2 + 1280;             // [2buf][32][8]    compact

    // stage x(0) (dup) + prefetch x(1)
    const float2* x2 = (const float2*)x;
    float2 xv = make_float2(0.f, 0.f);
    if (wsub == 0 && lane < 8) {
        float2 x0 = x2[(size_t)(sBase + lane) * Tt];
        *(u64*)&z1x[2 * lane]      = pk(x0.x, x0.x);
        *(u64*)&z1x[20 + 2 * lane] = pk(x0.y, x0.y);
        xv = x2[(size_t)(sBase + lane) * Tt + 1];
    }

    // biases as natural u64 gate-pairs
    const ulonglong2 b1 = *(const ulonglong2*)&sm[OB1 + u * 4];
    const ulonglong2 b2 = *(const ulonglong2*)&sm[OB2 + u * 4];
    const float bo = (lane < FOUT) ? sm[OBO + lane] : 0.f;
    const u64  bod = pk(bo, bo);

    float c1[4] = {0.f,0.f,0.f,0.f}, c2[4] = {0.f,0.f,0.f,0.f};
    __syncthreads();

    for (int t = 0; t < Tt; t++) {
        const int par = t & 1;
        const float* xrd  = z1x + par * 40;
        const float* h1rd = z1h + (par ^ 1) * 640;
        float*       h1wr = z1h + par * 640;
        const float* h2rd = z2h2 + (par ^ 1) * 640;
        float*       h2wr = z2h2 + par * 640;
        const float* h2cr = h2c + (par ^ 1) * 256;
        float*       h2cw = h2c + par * 256;

        // ---- 1. layer-1 accumulate ----
        u64 aig[4], afo[4];
        #pragma unroll
        for (int s = 0; s < 4; s++) { aig[s] = b1.x; afo[s] = b1.y; }
        #pragma unroll
        for (int k = 0; k < 2; k++) {
            ulonglong2 wv = *(const ulonglong2*)&sm[OW1 + (k * 32 + u) * 4];
            ulonglong2 zA = *(const ulonglong2*)&xrd[k * 20 + 8 * ph];
            ulonglong2 zB = *(const ulonglong2*)&xrd[k * 20 + 8 * ph + 4];
            u64 zp[4] = { zA.x, zA.y, zB.x, zB.y };
            #pragma unroll
            for (int s = 0; s < 4; s++) {
                aig[s] = fma2(wv.x, zp[s], aig[s]);
                afo[s] = fma2(wv.y, zp[s], afo[s]);
            }
        }
        #pragma unroll 8
        for (int k = 0; k < 32; k++) {
            ulonglong2 wv = *(const ulonglong2*)&sm[OW1 + ((k + 2) * 32 + u) * 4];
            ulonglong2 zA = *(const ulonglong2*)&h1rd[k * 20 + 8 * ph];
            ulonglong2 zB = *(const ulonglong2*)&h1rd[k * 20 + 8 * ph + 4];
            u64 zp[4] = { zA.x, zA.y, zB.x, zB.y };
            #pragma unroll
            for (int s = 0; s < 4; s++) {
                aig[s] = fma2(wv.x, zp[s], aig[s]);
                afo[s] = fma2(wv.y, zp[s], afo[s]);
            }
        }

        // ---- 2. layer-2 part B: h2(t-1) ----
        u64 dig[4], dfo[4];
        #pragma unroll
        for (int s = 0; s < 4; s++) { dig[s] = b2.x; dfo[s] = b2.y; }
        #pragma unroll 8
        for (int k = 0; k < 32; k++) {
            ulonglong2 wv = *(const ulonglong2*)&sm[OW2 + ((32 + k) * 32 + u) * 4];
            ulonglong2 zA = *(const ulonglong2*)&h2rd[k * 20 + 8 * ph];
            ulonglong2 zB = *(const ulonglong2*)&h2rd[k * 20 + 8 * ph + 4];
            u64 zp[4] = { zA.x, zA.y, zB.x, zB.y };
            #pragma unroll
            for (int s = 0; s < 4; s++) {
                dig[s] = fma2(wv.x, zp[s], dig[s]);
                dfo[s] = fma2(wv.y, zp[s], dfo[s]);
            }
        }

        // ---- 3. layer-1 epilogue + publish h1 (dup) ----
        #pragma unroll
        for (int s = 0; s < 4; s++) {
            float h = lstm_epi_s(aig[s], afo[s], c1[s]);
            *(u64*)&h1wr[u * 20 + 8 * ph + 2 * s] = pk(h, h);
        }

        // ---- 4. stage x(t+1), prefetch x(t+2) ----
        if (wsub == 0 && lane < 8) {
            float* xwr = z1x + (par ^ 1) * 40;
            *(u64*)&xwr[2 * lane]      = pk(xv.x, xv.x);
            *(u64*)&xwr[20 + 2 * lane] = pk(xv.y, xv.y);
            if (t + 2 < Tt) xv = x2[(size_t)(sBase + lane) * Tt + t + 2];
        }
        GBAR(bid);   // h1 visible within group

        // ---- 5. layer-2 part A: h1(t) ----
        #pragma unroll 8
        for (int k = 0; k < 32; k++) {
            ulonglong2 wv = *(const ulonglong2*)&sm[OW2 + (k * 32 + u) * 4];
            ulonglong2 zA = *(const ulonglong2*)&h1wr[k * 20 + 8 * ph];
            ulonglong2 zB = *(const ulonglong2*)&h1wr[k * 20 + 8 * ph + 4];
            u64 zp[4] = { zA.x, zA.y, zB.x, zB.y };
            #pragma unroll
            for (int s = 0; s < 4; s++) {
                dig[s] = fma2(wv.x, zp[s], dig[s]);
                dfo[s] = fma2(wv.y, zp[s], dfo[s]);
            }
        }

        // ---- 6. layer-2 epilogue; publish h2 dup + compact ----
        float h2s[4];
        #pragma unroll
        for (int s = 0; s < 4; s++)
            h2s[s] = lstm_epi_s(dig[s], dfo[s], c2[s]);
        #pragma unroll
        for (int s = 0; s < 4; s++)
            *(u64*)&h2wr[u * 20 + 8 * ph + 2 * s] = pk(h2s[s], h2s[s]);
        *(float4*)&h2cw[u * 8 + 4 * ph] = make_float4(h2s[0], h2s[1], h2s[2], h2s[3]);

        // ---- 7. deferred head(t-1): reads compact h2(t-1) ----
        if (t > 0 && lane < FOUT) {
            u64 acc0 = bod, acc1 = bod;
            const int pO = wsub * 2;
            #pragma unroll 8
            for (int k = 0; k < 32; k++) {
                float wo = sm[OWO + k * FOUT + lane];
                u64 wd = pk(wo, wo);
                ulonglong2 zz = *(const ulonglong2*)&h2cr[k * 8 + pO * 2];
                acc0 = fma2(wd, zz.x, acc0);
                acc1 = fma2(wd, zz.y, acc1);
            }
            float o0, o1;
            size_t rbase = ((size_t)(sBase + 4 * wsub) * Tt + (t - 1)) * FOUT + lane;
            upk(acc0, o0, o1);
            out[rbase]                          = o0;
            out[rbase + (size_t)Tt * FOUT]      = o1;
            upk(acc1, o0, o1);
            out[rbase + 2 * (size_t)Tt * FOUT]  = o0;
            out[rbase + 3 * (size_t)Tt * FOUT]  = o1;
        }
        GBAR(bid);   // h2 visible; state buffers safe to flip
    }

    // ---- final head: t = Tt-1 ----
    {
        const float* hc = h2c + ((Tt - 1) & 1) * 256;
        if (lane < FOUT) {
            u64 acc0 = bod, acc1 = bod;
            const int pO = wsub * 2;
            #pragma unroll 8
            for (int k = 0; k < 32; k++) {
                float wo = sm[OWO + k * FOUT + lane];
                u64 wd = pk(wo, wo);
                ulonglong2 zz = *(const ulonglong2*)&hc[k * 8 + pO * 2];
                acc0 = fma2(wd, zz.x, acc0);
                acc1 = fma2(wd, zz.y, acc1);
            }
            float o0, o1;
            size_t rbase = ((size_t)(sBase + 4 * wsub) * Tt + (Tt - 1)) * FOUT + lane;
            upk(acc0, o0, o1);
            out[rbase]                          = o0;
            out[rbase + (size_t)Tt * FOUT]      = o1;
            upk(acc1, o0, o1);
            out[rbase + 2 * (size_t)Tt * FOUT]  = o0;
            out[rbase + 3 * (size_t)Tt * FOUT]  = o1;
        }
    }
}

extern "C" void kernel_launch(void* const* d_in, const int* in_sizes, int n_in,
                              void* d_out, int out_size) {
    const float* x    = (const float*)d_in[0];
    const float* Wih1 = (const float*)d_in[1];
    const float* Whh1 = (const float*)d_in[2];
    const float* bih1 = (const float*)d_in[3];
    const float* bhh1 = (const float*)d_in[4];
    const float* Wih2 = (const float*)d_in[5];
    const float* Whh2 = (const float*)d_in[6];
    const float* bih2 = (const float*)d_in[7];
    const float* bhh2 = (const float*)d_in[8];
    const float* Wout = (const float*)d_in[9];
    const float* bout = (const float*)d_in[10];
    float* out = (float*)d_out;

    cudaFuncSetAttribute(lstm_seq_kernel,
                         cudaFuncAttributeMaxDynamicSharedMemorySize, SMEM_BYTES);
    lstm_seq_kernel<<<NBLK, 256, SMEM_BYTES>>>(
        x, Wih1, Whh1, bih1, bhh1, Wih2, Whh2, bih2, bhh2, Wout, bout, out);
}

// round 7
// speedup vs baseline: 1.0381x; 1.0381x over previous
#include <cuda_runtime.h>

typedef unsigned long long u64;

#define Bsz   4096
#define Tt    512
#define HID   32
#define FOUT  20
#define WARPS 8
#define PAIRS 2                    // f32x2 pairs per warp -> 4 samples/warp
#define SPW   (PAIRS * 2)          // samples per warp
#define SPB   (WARPS * SPW)        // 32 samples per block
#define NBLK  (Bsz / SPB)          // 128 blocks

// ---- shared memory layout (in floats) ----
#define OW1  0                      // [34][32][4]  L1 weights, gate-packed float4
#define OW2  (OW1 + 34*32*4)        // [64][32][4]  L2 weights (ih2|hh2 concat)
#define OWO  (OW2 + 64*32*4)        // [32][20]     W_out transposed
#define OB1  (OWO + 32*20)          // [32][4]      b1 gate-packed
#define OB2  (OB1 + 32*4)           // [32][4]
#define OBO  (OB2 + 32*4)           // [20] pad 32
#define OZ1  (OBO + 32)             // [WARPS][34][4]  rows: x0,x1,h1(32); cols: s0,s1,s2,s3
#define OZ2  (OZ1 + WARPS*34*4)     // [WARPS][64][4]  rows: h1(32) | h2(32)
#define SMEM_FLOATS (OZ2 + WARPS*64*4)
#define SMEM_BYTES  (SMEM_FLOATS * 4)

__device__ __forceinline__ u64 pk(float lo, float hi) {
    u64 r; asm("mov.b64 %0, {%1, %2};" : "=l"(r) : "f"(lo), "f"(hi)); return r;
}
__device__ __forceinline__ void upk(u64 v, float& lo, float& hi) {
    asm("mov.b64 {%0, %1}, %2;" : "=f"(lo), "=f"(hi) : "l"(v));
}
__device__ __forceinline__ u64 fma2(u64 a, u64 b, u64 c) {
    u64 d; asm("fma.rn.f32x2 %0, %1, %2, %3;" : "=l"(d) : "l"(a), "l"(b), "l"(c)); return d;
}
__device__ __forceinline__ u64 mul2(u64 a, u64 b) {
    u64 d; asm("mul.rn.f32x2 %0, %1, %2;" : "=l"(d) : "l"(a), "l"(b)); return d;
}
__device__ __forceinline__ float sigmf(float x) {
    return __fdividef(1.f, 1.f + __expf(-x));
}
__device__ __forceinline__ float tanhfast(float x) {
    float a = fabsf(x);
    float e = __expf(-2.f * a);
    float t = __fdividef(1.f - e, 1.f + e);
    return copysignf(t, x);
}

// LSTM gate epilogue for one f32x2 pair (identical to R1's proven version).
__device__ __forceinline__ u64 lstm_epi(u64 ai, u64 af, u64 ag, u64 ao, u64& c) {
    float i0, i1, f0, f1, g0, g1, o0, o1;
    upk(ai, i0, i1); upk(af, f0, f1); upk(ag, g0, g1); upk(ao, o0, o1);
    i0 = sigmf(i0); i1 = sigmf(i1);
    f0 = sigmf(f0); f1 = sigmf(f1);
    g0 = tanhfast(g0); g1 = tanhfast(g1);
    o0 = sigmf(o0); o1 = sigmf(o1);
    u64 ig = mul2(pk(i0, i1), pk(g0, g1));
    c = fma2(pk(f0, f1), c, ig);
    float ca, cb; upk(c, ca, cb);
    return pk(o0 * tanhfast(ca), o1 * tanhfast(cb));
}

__global__ void __launch_bounds__(WARPS * 32, 1)
lstm_seq_kernel(const float* __restrict__ x,
                const float* __restrict__ Wih1, const float* __restrict__ Whh1,
                const float* __restrict__ bih1, const float* __restrict__ bhh1,
                const float* __restrict__ Wih2, const float* __restrict__ Whh2,
                const float* __restrict__ bih2, const float* __restrict__ bhh2,
                const float* __restrict__ Wout, const float* __restrict__ bout,
                float* __restrict__ out)
{
    extern __shared__ float sm[];
    const int tid = threadIdx.x;

    // ---- stage weights (transposed, gate-packed) -- identical to R1 ----
    for (int idx = tid; idx < 34 * 32; idx += blockDim.x) {
        int k = idx >> 5, j = idx & 31;
        #pragma unroll
        for (int g = 0; g < 4; g++) {
            float v = (k < 2) ? Wih1[(g * 32 + j) * 2 + k]
                              : Whh1[(g * 32 + j) * 32 + (k - 2)];
            sm[OW1 + idx * 4 + g] = v;
        }
    }
    for (int idx = tid; idx < 64 * 32; idx += blockDim.x) {
        int k = idx >> 5, j = idx & 31;
        #pragma unroll
        for (int g = 0; g < 4; g++) {
            float v = (k < 32) ? Wih2[(g * 32 + j) * 32 + k]
                               : Whh2[(g * 32 + j) * 32 + (k - 32)];
            sm[OW2 + idx * 4 + g] = v;
        }
    }
    for (int idx = tid; idx < 32 * 20; idx += blockDim.x) {
        int k = idx / 20, o = idx % 20;
        sm[OWO + idx] = Wout[o * 32 + k];
    }
    for (int idx = tid; idx < 32; idx += blockDim.x) {
        #pragma unroll
        for (int g = 0; g < 4; g++) {
            sm[OB1 + idx * 4 + g] = bih1[g * 32 + idx] + bhh1[g * 32 + idx];
            sm[OB2 + idx * 4 + g] = bih2[g * 32 + idx] + bhh2[g * 32 + idx];
        }
    }
    for (int idx = tid; idx < FOUT; idx += blockDim.x) sm[OBO + idx] = bout[idx];
    // zero state exchange buffers (h, c initial state = 0)
    for (int idx = tid; idx < WARPS * 34 * 4; idx += blockDim.x) sm[OZ1 + idx] = 0.f;
    for (int idx = tid; idx < WARPS * 64 * 4; idx += blockDim.x) sm[OZ2 + idx] = 0.f;
    __syncthreads();

    const int w    = tid >> 5;
    const int lane = tid & 31;
    const int sWarp = blockIdx.x * SPB + w * SPW;   // first sample of this warp

    float* z1 = sm + OZ1 + w * 34 * 4;    // [34 rows][4 samples]
    float* z2 = sm + OZ2 + w * 64 * 4;    // [64 rows][4 samples]

    u64 c1[PAIRS], c2[PAIRS];
    #pragma unroll
    for (int p = 0; p < PAIRS; p++) { c1[p] = 0ull; c2[p] = 0ull; }

    // prefetch x(t=0): lanes 0..SPW-1 each own one sample
    float2 xv = make_float2(0.f, 0.f);
    if (lane < SPW) xv = ((const float2*)x)[(size_t)(sWarp + lane) * Tt];

    const float4 bv1 = *(const float4*)&sm[OB1 + lane * 4];
    const float4 bv2 = *(const float4*)&sm[OB2 + lane * 4];
    const float  bo  = (lane < FOUT) ? sm[OBO + lane] : 0.f;

    for (int t = 0; t < Tt; t++) {
        // ---- store x_t into z1 rows 0..1 (row-major: [row][sample]) ----
        if (lane < SPW) {
            z1[0 * 4 + lane] = xv.x;
            z1[1 * 4 + lane] = xv.y;
        }
        __syncwarp();
        if (lane < SPW && t + 1 < Tt)
            xv = ((const float2*)x)[(size_t)(sWarp + lane) * Tt + t + 1];

        // ---- layer 1 accumulate: gates[g][pair] over k=0..33 ----
        u64 a0[PAIRS], a1[PAIRS], a2[PAIRS], a3[PAIRS];
        #pragma unroll
        for (int p = 0; p < PAIRS; p++) {
            a0[p] = pk(bv1.x, bv1.x); a1[p] = pk(bv1.y, bv1.y);
            a2[p] = pk(bv1.z, bv1.z); a3[p] = pk(bv1.w, bv1.w);
        }
        #pragma unroll 2
        for (int k = 0; k < 34; k++) {
            float4 wv = *(const float4*)&sm[OW1 + (k * 32 + lane) * 4];
            u64 w0 = pk(wv.x, wv.x), w1 = pk(wv.y, wv.y);
            u64 w2 = pk(wv.z, wv.z), w3 = pk(wv.w, wv.w);
            ulonglong2 zz = *(const ulonglong2*)&z1[k * 4];   // one LDS.128 broadcast
            u64 zp[PAIRS] = { zz.x, zz.y };
            #pragma unroll
            for (int p = 0; p < PAIRS; p++) {
                a0[p] = fma2(w0, zp[p], a0[p]);
                a1[p] = fma2(w1, zp[p], a1[p]);
                a2[p] = fma2(w2, zp[p], a2[p]);
                a3[p] = fma2(w3, zp[p], a3[p]);
            }
        }
        __syncwarp();   // all lanes done reading z1 before h1 writes

        // ---- layer 1 epilogue: new h1 -> z1 row (2+lane) and z2 row lane ----
        {
            float4 hv;
            u64 hp0 = lstm_epi(a0[0], a1[0], a2[0], a3[0], c1[0]);
            u64 hp1 = lstm_epi(a0[1], a1[1], a2[1], a3[1], c1[1]);
            upk(hp0, hv.x, hv.y); upk(hp1, hv.z, hv.w);
            *(float4*)&z1[(2 + lane) * 4] = hv;
            *(float4*)&z2[lane * 4]       = hv;
        }
        __syncwarp();   // h1 visible

        // ---- layer 2 accumulate over k=0..63 (h1 | h2_prev) ----
        u64 d0[PAIRS], d1[PAIRS], d2[PAIRS], d3[PAIRS];
        #pragma unroll
        for (int p = 0; p < PAIRS; p++) {
            d0[p] = pk(bv2.x, bv2.x); d1[p] = pk(bv2.y, bv2.y);
            d2[p] = pk(bv2.z, bv2.z); d3[p] = pk(bv2.w, bv2.w);
        }
        #pragma unroll 2
        for (int k = 0; k < 64; k++) {
            float4 wv = *(const float4*)&sm[OW2 + (k * 32 + lane) * 4];
            u64 w0 = pk(wv.x, wv.x), w1 = pk(wv.y, wv.y);
            u64 w2 = pk(wv.z, wv.z), w3 = pk(wv.w, wv.w);
            ulonglong2 zz = *(const ulonglong2*)&z2[k * 4];   // one LDS.128 broadcast
            u64 zp[PAIRS] = { zz.x, zz.y };
            #pragma unroll
            for (int p = 0; p < PAIRS; p++) {
                d0[p] = fma2(w0, zp[p], d0[p]);
                d1[p] = fma2(w1, zp[p], d1[p]);
                d2[p] = fma2(w2, zp[p], d2[p]);
                d3[p] = fma2(w3, zp[p], d3[p]);
            }
        }
        __syncwarp();   // all lanes done reading z2 before h2 writes

        // ---- layer 2 epilogue: new h2 -> z2 row (32+lane) ----
        {
            float4 hv;
            u64 hp0 = lstm_epi(d0[0], d1[0], d2[0], d3[0], c2[0]);
            u64 hp1 = lstm_epi(d0[1], d1[1], d2[1], d3[1], c2[1]);
            upk(hp0, hv.x, hv.y); upk(hp1, hv.z, hv.w);
            *(float4*)&z2[(32 + lane) * 4] = hv;
        }
        __syncwarp();   // h2 visible

        // ---- output head: lanes 0..19 compute out[o] = h2 . Wout[o] + b ----
        if (lane < FOUT) {
            u64 acc0 = pk(bo, bo), acc1 = pk(bo, bo);
            #pragma unroll 4
            for (int k = 0; k < 32; k++) {
                float wo = sm[OWO + k * FOUT + lane];
                u64 wd = pk(wo, wo);
                ulonglong2 zz = *(const ulonglong2*)&z2[(32 + k) * 4];
                acc0 = fma2(wd, zz.x, acc0);
                acc1 = fma2(wd, zz.y, acc1);
            }
            float oa, ob;
            size_t rbase = ((size_t)sWarp * Tt + t) * FOUT + lane;
            upk(acc0, oa, ob);
            out[rbase]                         = oa;
            out[rbase + (size_t)Tt * FOUT]     = ob;
            upk(acc1, oa, ob);
            out[rbase + 2 * (size_t)Tt * FOUT] = oa;
            out[rbase + 3 * (size_t)Tt * FOUT] = ob;
        }
        // next iteration's syncwarps cover cross-step hazards
    }
}

extern "C" void kernel_launch(void* const* d_in, const int* in_sizes, int n_in,
                              void* d_out, int out_size) {
    const float* x    = (const float*)d_in[0];
    const float* Wih1 = (const float*)d_in[1];
    const float* Whh1 = (const float*)d_in[2];
    const float* bih1 = (const float*)d_in[3];
    const float* bhh1 = (const float*)d_in[4];
    const float* Wih2 = (const float*)d_in[5];
    const float* Whh2 = (const float*)d_in[6];
    const float* bih2 = (const float*)d_in[7];
    const float* bhh2 = (const float*)d_in[8];
    const float* Wout = (const float*)d_in[9];
    const float* bout = (const float*)d_in[10];
    float* out = (float*)d_out;

    cudaFuncSetAttribute(lstm_seq_kernel,
                         cudaFuncAttributeMaxDynamicSharedMemorySize, SMEM_BYTES);
    lstm_seq_kernel<<<NBLK, WARPS * 32, SMEM_BYTES>>>(
        x, Wih1, Whh1, bih1, bhh1, Wih2, Whh2, bih2, bhh2, Wout, bout, out);
}

// round 8
// speedup vs baseline: 1.0545x; 1.0158x over previous
#include <cuda_runtime.h>

typedef unsigned long long u64;

#define Bsz   4096
#define Tt    512
#define HID   32
#define FOUT  20
#define WARPS 8
#define PAIRS 2                    // f32x2 pairs per warp -> 4 samples/warp
#define SPW   (PAIRS * 2)          // samples per warp
#define SPB   (WARPS * SPW)        // 32 samples per block
#define NBLK  (Bsz / SPB)          // 128 blocks

// ---- shared memory layout (in floats) ---- (identical to R1)
#define OW1  0                      // [34][32][4]  L1 weights, gate-packed float4
#define OW2  (OW1 + 34*32*4)        // [64][32][4]  L2 weights (ih2|hh2 concat)
#define OWO  (OW2 + 64*32*4)        // [32][20]     W_out transposed
#define OB1  (OWO + 32*20)          // [32][4]      b1 gate-packed
#define OB2  (OB1 + 32*4)           // [32][4]
#define OBO  (OB2 + 32*4)           // [20]
#define OZ1  (OBO + 20)             // [WARPS][PAIRS][34][2]  (x0,x1,h1_prev) pairs
#define OZ2  (OZ1 + WARPS*PAIRS*34*2) // [WARPS][PAIRS][64][2]  (h1_cur | h2_prev) pairs
#define SMEM_FLOATS (OZ2 + WARPS*PAIRS*64*2)
#define SMEM_BYTES  (SMEM_FLOATS * 4)

__device__ __forceinline__ u64 pk(float lo, float hi) {
    u64 r; asm("mov.b64 %0, {%1, %2};" : "=l"(r) : "f"(lo), "f"(hi)); return r;
}
__device__ __forceinline__ void upk(u64 v, float& lo, float& hi) {
    asm("mov.b64 {%0, %1}, %2;" : "=f"(lo), "=f"(hi) : "l"(v));
}
__device__ __forceinline__ u64 fma2(u64 a, u64 b, u64 c) {
    u64 d; asm("fma.rn.f32x2 %0, %1, %2, %3;" : "=l"(d) : "l"(a), "l"(b), "l"(c)); return d;
}
__device__ __forceinline__ u64 mul2(u64 a, u64 b) {
    u64 d; asm("mul.rn.f32x2 %0, %1, %2;" : "=l"(d) : "l"(a), "l"(b)); return d;
}
__device__ __forceinline__ float sigmf(float x) {
    return __fdividef(1.f, 1.f + __expf(-x));
}
__device__ __forceinline__ float tanhfast(float x) {
    float a = fabsf(x);
    float e = __expf(-2.f * a);
    float t = __fdividef(1.f - e, 1.f + e);
    return copysignf(t, x);
}

// LSTM gate epilogue for one f32x2 pair (identical to R1).
__device__ __forceinline__ u64 lstm_epi(u64 ai, u64 af, u64 ag, u64 ao, u64& c) {
    float i0, i1, f0, f1, g0, g1, o0, o1;
    upk(ai, i0, i1); upk(af, f0, f1); upk(ag, g0, g1); upk(ao, o0, o1);
    i0 = sigmf(i0); i1 = sigmf(i1);
    f0 = sigmf(f0); f1 = sigmf(f1);
    g0 = tanhfast(g0); g1 = tanhfast(g1);
    o0 = sigmf(o0); o1 = sigmf(o1);
    u64 ig = mul2(pk(i0, i1), pk(g0, g1));
    c = fma2(pk(f0, f1), c, ig);
    float ca, cb; upk(c, ca, cb);
    return pk(o0 * tanhfast(ca), o1 * tanhfast(cb));
}

__global__ void __launch_bounds__(WARPS * 32, 1)
lstm_seq_kernel(const float* __restrict__ x,
                const float* __restrict__ Wih1, const float* __restrict__ Whh1,
                const float* __restrict__ bih1, const float* __restrict__ bhh1,
                const float* __restrict__ Wih2, const float* __restrict__ Whh2,
                const float* __restrict__ bih2, const float* __restrict__ bhh2,
                const float* __restrict__ Wout, const float* __restrict__ bout,
                float* __restrict__ out)
{
    extern __shared__ float sm[];
    const int tid = threadIdx.x;

    // ---- stage weights (transposed, gate-packed) -- identical to R1 ----
    for (int idx = tid; idx < 34 * 32; idx += blockDim.x) {
        int k = idx >> 5, j = idx & 31;
        #pragma unroll
        for (int g = 0; g < 4; g++) {
            float v = (k < 2) ? Wih1[(g * 32 + j) * 2 + k]
                              : Whh1[(g * 32 + j) * 32 + (k - 2)];
            sm[OW1 + idx * 4 + g] = v;
        }
    }
    for (int idx = tid; idx < 64 * 32; idx += blockDim.x) {
        int k = idx >> 5, j = idx & 31;
        #pragma unroll
        for (int g = 0; g < 4; g++) {
            float v = (k < 32) ? Wih2[(g * 32 + j) * 32 + k]
                               : Whh2[(g * 32 + j) * 32 + (k - 32)];
            sm[OW2 + idx * 4 + g] = v;
        }
    }
    for (int idx = tid; idx < 32 * 20; idx += blockDim.x) {
        int k = idx / 20, o = idx % 20;
        sm[OWO + idx] = Wout[o * 32 + k];
    }
    for (int idx = tid; idx < 32; idx += blockDim.x) {
        #pragma unroll
        for (int g = 0; g < 4; g++) {
            sm[OB1 + idx * 4 + g] = bih1[g * 32 + idx] + bhh1[g * 32 + idx];
            sm[OB2 + idx * 4 + g] = bih2[g * 32 + idx] + bhh2[g * 32 + idx];
        }
    }
    for (int idx = tid; idx < FOUT; idx += blockDim.x) sm[OBO + idx] = bout[idx];
    // zero state exchange buffers (h, c initial state = 0)
    for (int idx = tid; idx < WARPS * PAIRS * 34 * 2; idx += blockDim.x) sm[OZ1 + idx] = 0.f;
    for (int idx = tid; idx < WARPS * PAIRS * 64 * 2; idx += blockDim.x) sm[OZ2 + idx] = 0.f;
    __syncthreads();

    const int w    = tid >> 5;
    const int lane = tid & 31;
    const int sWarp = blockIdx.x * SPB + w * SPW;   // first sample of this warp

    float* z1 = sm + OZ1 + (w * PAIRS) * 34 * 2;    // pair p at +p*68
    float* z2 = sm + OZ2 + (w * PAIRS) * 64 * 2;    // pair p at +p*128

    u64 c1[PAIRS], c2[PAIRS];
    #pragma unroll
    for (int p = 0; p < PAIRS; p++) { c1[p] = 0ull; c2[p] = 0ull; }

    // prefetch x(t=0): lanes 0..SPW-1 each own one sample
    float2 xv = make_float2(0.f, 0.f);
    if (lane < SPW) xv = ((const float2*)x)[(size_t)(sWarp + lane) * Tt];

    const float4 bv1 = *(const float4*)&sm[OB1 + lane * 4];
    const float4 bv2 = *(const float4*)&sm[OB2 + lane * 4];
    const float  bo  = (lane < FOUT) ? sm[OBO + lane] : 0.f;

    for (int t = 0; t < Tt; t++) {
        // ---- store x_t into z1 slots 0..1 ----
        if (lane < SPW) {
            int p = lane >> 1, half = lane & 1;
            z1[(p * 34 + 0) * 2 + half] = xv.x;
            z1[(p * 34 + 1) * 2 + half] = xv.y;
        }
        __syncwarp();
        if (lane < SPW && t + 1 < Tt)
            xv = ((const float2*)x)[(size_t)(sWarp + lane) * Tt + t + 1];

        // ---- layer 1 accumulate: gates[g][pair] over k=0..33 ----
        u64 a0[PAIRS], a1[PAIRS], a2[PAIRS], a3[PAIRS];
        #pragma unroll
        for (int p = 0; p < PAIRS; p++) {
            a0[p] = pk(bv1.x, bv1.x); a1[p] = pk(bv1.y, bv1.y);
            a2[p] = pk(bv1.z, bv1.z); a3[p] = pk(bv1.w, bv1.w);
        }
        #pragma unroll 2
        for (int k = 0; k < 34; k++) {
            float4 wv = *(const float4*)&sm[OW1 + (k * 32 + lane) * 4];
            u64 w0 = pk(wv.x, wv.x), w1 = pk(wv.y, wv.y);
            u64 w2 = pk(wv.z, wv.z), w3 = pk(wv.w, wv.w);
            #pragma unroll
            for (int p = 0; p < PAIRS; p++) {
                u64 zp = *(const u64*)&z1[(p * 34 + k) * 2];
                a0[p] = fma2(w0, zp, a0[p]);
                a1[p] = fma2(w1, zp, a1[p]);
                a2[p] = fma2(w2, zp, a2[p]);
                a3[p] = fma2(w3, zp, a3[p]);
            }
        }

        // ---- layer 2 part B: h2(t-1) rows (k=32..63) -- independent of L1 epilogue,
        //      z2[32..63] untouched since previous step's publish. Overlaps the MUFU chain.
        u64 d0[PAIRS], d1[PAIRS], d2[PAIRS], d3[PAIRS];
        #pragma unroll
        for (int p = 0; p < PAIRS; p++) {
            d0[p] = pk(bv2.x, bv2.x); d1[p] = pk(bv2.y, bv2.y);
            d2[p] = pk(bv2.z, bv2.z); d3[p] = pk(bv2.w, bv2.w);
        }
        #pragma unroll 2
        for (int k = 32; k < 64; k++) {
            float4 wv = *(const float4*)&sm[OW2 + (k * 32 + lane) * 4];
            u64 w0 = pk(wv.x, wv.x), w1 = pk(wv.y, wv.y);
            u64 w2 = pk(wv.z, wv.z), w3 = pk(wv.w, wv.w);
            #pragma unroll
            for (int p = 0; p < PAIRS; p++) {
                u64 zp = *(const u64*)&z2[(p * 64 + k) * 2];
                d0[p] = fma2(w0, zp, d0[p]);
                d1[p] = fma2(w1, zp, d1[p]);
                d2[p] = fma2(w2, zp, d2[p]);
                d3[p] = fma2(w3, zp, d3[p]);
            }
        }
        __syncwarp();   // all lanes done reading z1 h-rows before h1 writes

        // ---- layer 1 epilogue: new h1 -> z1[2+lane] (next t) and z2[lane] (layer 2 input) ----
        #pragma unroll
        for (int p = 0; p < PAIRS; p++) {
            u64 hp = lstm_epi(a0[p], a1[p], a2[p], a3[p], c1[p]);
            *(u64*)&z1[(p * 34 + 2 + lane) * 2] = hp;
            *(u64*)&z2[(p * 64 + lane) * 2]     = hp;
        }
        __syncwarp();   // h1 visible

        // ---- layer 2 part A: h1(t) rows (k=0..31) ----
        #pragma unroll 2
        for (int k = 0; k < 32; k++) {
            float4 wv = *(const float4*)&sm[OW2 + (k * 32 + lane) * 4];
            u64 w0 = pk(wv.x, wv.x), w1 = pk(wv.y, wv.y);
            u64 w2 = pk(wv.z, wv.z), w3 = pk(wv.w, wv.w);
            #pragma unroll
            for (int p = 0; p < PAIRS; p++) {
                u64 zp = *(const u64*)&z2[(p * 64 + k) * 2];
                d0[p] = fma2(w0, zp, d0[p]);
                d1[p] = fma2(w1, zp, d1[p]);
                d2[p] = fma2(w2, zp, d2[p]);
                d3[p] = fma2(w3, zp, d3[p]);
            }
        }
        __syncwarp();   // all lanes done reading z2[32..63] (part B) before h2 writes

        // ---- layer 2 epilogue: new h2 -> z2 row (32+lane) ----
        #pragma unroll
        for (int p = 0; p < PAIRS; p++) {
            u64 hp = lstm_epi(d0[p], d1[p], d2[p], d3[p], c2[p]);
            *(u64*)&z2[(p * 64 + 32 + lane) * 2] = hp;
        }
        __syncwarp();   // h2 visible

        // ---- output head: lanes 0..19 compute out[o] = h2 . Wout[o] + b ----
        if (lane < FOUT) {
            u64 acc[PAIRS];
            #pragma unroll
            for (int p = 0; p < PAIRS; p++) acc[p] = pk(bo, bo);
            #pragma unroll 4
            for (int k = 0; k < 32; k++) {
                float wo = sm[OWO + k * FOUT + lane];
                u64 wd = pk(wo, wo);
                #pragma unroll
                for (int p = 0; p < PAIRS; p++) {
                    u64 zp = *(const u64*)&z2[(p * 64 + 32 + k) * 2];
                    acc[p] = fma2(wd, zp, acc[p]);
                }
            }
            #pragma unroll
            for (int p = 0; p < PAIRS; p++) {
                float oa, ob; upk(acc[p], oa, ob);
                int sa = sWarp + 2 * p;
                out[((size_t)sa * Tt + t) * FOUT + lane]       = oa;
                out[((size_t)(sa + 1) * Tt + t) * FOUT + lane] = ob;
            }
        }
        // next iteration's syncwarps cover the z2 read/write hazard across steps
    }
}

extern "C" void kernel_launch(void* const* d_in, const int* in_sizes, int n_in,
                              void* d_out, int out_size) {
    const float* x    = (const float*)d_in[0];
    const float* Wih1 = (const float*)d_in[1];
    const float* Whh1 = (const float*)d_in[2];
    const float* bih1 = (const float*)d_in[3];
    const float* bhh1 = (const float*)d_in[4];
    const float* Wih2 = (const float*)d_in[5];
    const float* Whh2 = (const float*)d_in[6];
    const float* bih2 = (const float*)d_in[7];
    const float* bhh2 = (const float*)d_in[8];
    const float* Wout = (const float*)d_in[9];
    const float* bout = (const float*)d_in[10];
    float* out = (float*)d_out;

    cudaFuncSetAttribute(lstm_seq_kernel,
                         cudaFuncAttributeMaxDynamicSharedMemorySize, SMEM_BYTES);
    lstm_seq_kernel<<<NBLK, WARPS * 32, SMEM_BYTES>>>(
        x, Wih1, Whh1, bih1, bhh1, Wih2, Whh2, bih2, bhh2, Wout, bout, out);
}

// round 9
// speedup vs baseline: 1.0944x; 1.0379x over previous
#include <cuda_runtime.h>

typedef unsigned long long u64;

#define Bsz   4096
#define Tt    512
#define HID   32
#define FOUT  20
#define WARPS 8
#define PAIRS 2                    // f32x2 pairs per warp -> 4 samples/warp
#define SPW   (PAIRS * 2)          // samples per warp
#define SPB   (WARPS * SPW)        // 32 samples per block
#define NBLK  (Bsz / SPB)          // 128 blocks

// scratch for h2 trajectory: [sample][t][unit], b-major rows (row = s*Tt + t)
__device__ float h2buf[(size_t)Bsz * Tt * HID];   // 256 MB

// ---- shared memory layout (in floats) ---- (byte-identical to R1)
#define OW1  0                      // [34][32][4]  L1 weights, gate-packed float4
#define OW2  (OW1 + 34*32*4)        // [64][32][4]  L2 weights (ih2|hh2 concat)
#define OWO  (OW2 + 64*32*4)        // [32][20]     W_out transposed (unused; layout kept)
#define OB1  (OWO + 32*20)          // [32][4]      b1 gate-packed
#define OB2  (OB1 + 32*4)           // [32][4]
#define OBO  (OB2 + 32*4)           // [20]
#define OZ1  (OBO + 20)             // [WARPS][PAIRS][34][2]  (x0,x1,h1_prev) pairs
#define OZ2  (OZ1 + WARPS*PAIRS*34*2) // [WARPS][PAIRS][64][2]  (h1_cur | h2_prev) pairs
#define SMEM_FLOATS (OZ2 + WARPS*PAIRS*64*2)
#define SMEM_BYTES  (SMEM_FLOATS * 4)

__device__ __forceinline__ u64 pk(float lo, float hi) {
    u64 r; asm("mov.b64 %0, {%1, %2};" : "=l"(r) : "f"(lo), "f"(hi)); return r;
}
__device__ __forceinline__ void upk(u64 v, float& lo, float& hi) {
    asm("mov.b64 {%0, %1}, %2;" : "=f"(lo), "=f"(hi) : "l"(v));
}
__device__ __forceinline__ u64 fma2(u64 a, u64 b, u64 c) {
    u64 d; asm("fma.rn.f32x2 %0, %1, %2, %3;" : "=l"(d) : "l"(a), "l"(b), "l"(c)); return d;
}
__device__ __forceinline__ u64 mul2(u64 a, u64 b) {
    u64 d; asm("mul.rn.f32x2 %0, %1, %2;" : "=l"(d) : "l"(a), "l"(b)); return d;
}
__device__ __forceinline__ float sigmf(float x) {
    return __fdividef(1.f, 1.f + __expf(-x));
}
__device__ __forceinline__ float tanhfast(float x) {
    float a = fabsf(x);
    float e = __expf(-2.f * a);
    float t = __fdividef(1.f - e, 1.f + e);
    return copysignf(t, x);
}

// LSTM gate epilogue for one f32x2 pair (identical to R1).
__device__ __forceinline__ u64 lstm_epi(u64 ai, u64 af, u64 ag, u64 ao, u64& c) {
    float i0, i1, f0, f1, g0, g1, o0, o1;
    upk(ai, i0, i1); upk(af, f0, f1); upk(ag, g0, g1); upk(ao, o0, o1);
    i0 = sigmf(i0); i1 = sigmf(i1);
    f0 = sigmf(f0); f1 = sigmf(f1);
    g0 = tanhfast(g0); g1 = tanhfast(g1);
    o0 = sigmf(o0); o1 = sigmf(o1);
    u64 ig = mul2(pk(i0, i1), pk(g0, g1));
    c = fma2(pk(f0, f1), c, ig);
    float ca, cb; upk(c, ca, cb);
    return pk(o0 * tanhfast(ca), o1 * tanhfast(cb));
}

__global__ void __launch_bounds__(WARPS * 32, 1)
lstm_seq_kernel(const float* __restrict__ x,
                const float* __restrict__ Wih1, const float* __restrict__ Whh1,
                const float* __restrict__ bih1, const float* __restrict__ bhh1,
                const float* __restrict__ Wih2, const float* __restrict__ Whh2,
                const float* __restrict__ bih2, const float* __restrict__ bhh2,
                const float* __restrict__ Wout, const float* __restrict__ bout)
{
    extern __shared__ float sm[];
    const int tid = threadIdx.x;

    // ---- stage weights (transposed, gate-packed) -- identical to R1 ----
    for (int idx = tid; idx < 34 * 32; idx += blockDim.x) {
        int k = idx >> 5, j = idx & 31;
        #pragma unroll
        for (int g = 0; g < 4; g++) {
            float v = (k < 2) ? Wih1[(g * 32 + j) * 2 + k]
                              : Whh1[(g * 32 + j) * 32 + (k - 2)];
            sm[OW1 + idx * 4 + g] = v;
        }
    }
    for (int idx = tid; idx < 64 * 32; idx += blockDim.x) {
        int k = idx >> 5, j = idx & 31;
        #pragma unroll
        for (int g = 0; g < 4; g++) {
            float v = (k < 32) ? Wih2[(g * 32 + j) * 32 + k]
                               : Whh2[(g * 32 + j) * 32 + (k - 32)];
            sm[OW2 + idx * 4 + g] = v;
        }
    }
    for (int idx = tid; idx < 32 * 20; idx += blockDim.x) {
        int k = idx / 20, o = idx % 20;
        sm[OWO + idx] = Wout[o * 32 + k];
    }
    for (int idx = tid; idx < 32; idx += blockDim.x) {
        #pragma unroll
        for (int g = 0; g < 4; g++) {
            sm[OB1 + idx * 4 + g] = bih1[g * 32 + idx] + bhh1[g * 32 + idx];
            sm[OB2 + idx * 4 + g] = bih2[g * 32 + idx] + bhh2[g * 32 + idx];
        }
    }
    for (int idx = tid; idx < FOUT; idx += blockDim.x) sm[OBO + idx] = bout[idx];
    // zero state exchange buffers (h, c initial state = 0)
    for (int idx = tid; idx < WARPS * PAIRS * 34 * 2; idx += blockDim.x) sm[OZ1 + idx] = 0.f;
    for (int idx = tid; idx < WARPS * PAIRS * 64 * 2; idx += blockDim.x) sm[OZ2 + idx] = 0.f;
    __syncthreads();

    const int w    = tid >> 5;
    const int lane = tid & 31;
    const int sWarp = blockIdx.x * SPB + w * SPW;   // first sample of this warp

    float* z1 = sm + OZ1 + (w * PAIRS) * 34 * 2;    // pair p at +p*68
    float* z2 = sm + OZ2 + (w * PAIRS) * 64 * 2;    // pair p at +p*128

    u64 c1[PAIRS], c2[PAIRS];
    #pragma unroll
    for (int p = 0; p < PAIRS; p++) { c1[p] = 0ull; c2[p] = 0ull; }

    // prefetch x(t=0): lanes 0..SPW-1 each own one sample
    float2 xv = make_float2(0.f, 0.f);
    if (lane < SPW) xv = ((const float2*)x)[(size_t)(sWarp + lane) * Tt];

    const float4 bv1 = *(const float4*)&sm[OB1 + lane * 4];
    const float4 bv2 = *(const float4*)&sm[OB2 + lane * 4];

    for (int t = 0; t < Tt; t++) {
        // ---- store x_t into z1 slots 0..1 ----
        if (lane < SPW) {
            int p = lane >> 1, half = lane & 1;
            z1[(p * 34 + 0) * 2 + half] = xv.x;
            z1[(p * 34 + 1) * 2 + half] = xv.y;
        }
        __syncwarp();
        if (lane < SPW && t + 1 < Tt)
            xv = ((const float2*)x)[(size_t)(sWarp + lane) * Tt + t + 1];

        // ---- layer 1 accumulate: gates[g][pair] over k=0..33 ----
        u64 a0[PAIRS], a1[PAIRS], a2[PAIRS], a3[PAIRS];
        #pragma unroll
        for (int p = 0; p < PAIRS; p++) {
            a0[p] = pk(bv1.x, bv1.x); a1[p] = pk(bv1.y, bv1.y);
            a2[p] = pk(bv1.z, bv1.z); a3[p] = pk(bv1.w, bv1.w);
        }
        #pragma unroll 2
        for (int k = 0; k < 34; k++) {
            float4 wv = *(const float4*)&sm[OW1 + (k * 32 + lane) * 4];
            u64 w0 = pk(wv.x, wv.x), w1 = pk(wv.y, wv.y);
            u64 w2 = pk(wv.z, wv.z), w3 = pk(wv.w, wv.w);
            #pragma unroll
            for (int p = 0; p < PAIRS; p++) {
                u64 zp = *(const u64*)&z1[(p * 34 + k) * 2];
                a0[p] = fma2(w0, zp, a0[p]);
                a1[p] = fma2(w1, zp, a1[p]);
                a2[p] = fma2(w2, zp, a2[p]);
                a3[p] = fma2(w3, zp, a3[p]);
            }
        }
        __syncwarp();   // all lanes done reading z1 before h1 writes

        // ---- layer 1 epilogue: new h1 -> z1[2+lane] (next t) and z2[lane] ----
        #pragma unroll
        for (int p = 0; p < PAIRS; p++) {
            u64 hp = lstm_epi(a0[p], a1[p], a2[p], a3[p], c1[p]);
            *(u64*)&z1[(p * 34 + 2 + lane) * 2] = hp;
            *(u64*)&z2[(p * 64 + lane) * 2]     = hp;
        }
        __syncwarp();   // h1 visible

        // ---- layer 2 accumulate over k=0..63 (h1 | h2_prev) ----
        u64 d0[PAIRS], d1[PAIRS], d2[PAIRS], d3[PAIRS];
        #pragma unroll
        for (int p = 0; p < PAIRS; p++) {
            d0[p] = pk(bv2.x, bv2.x); d1[p] = pk(bv2.y, bv2.y);
            d2[p] = pk(bv2.z, bv2.z); d3[p] = pk(bv2.w, bv2.w);
        }
        #pragma unroll 2
        for (int k = 0; k < 64; k++) {
            float4 wv = *(const float4*)&sm[OW2 + (k * 32 + lane) * 4];
            u64 w0 = pk(wv.x, wv.x), w1 = pk(wv.y, wv.y);
            u64 w2 = pk(wv.z, wv.z), w3 = pk(wv.w, wv.w);
            #pragma unroll
            for (int p = 0; p < PAIRS; p++) {
                u64 zp = *(const u64*)&z2[(p * 64 + k) * 2];
                d0[p] = fma2(w0, zp, d0[p]);
                d1[p] = fma2(w1, zp, d1[p]);
                d2[p] = fma2(w2, zp, d2[p]);
                d3[p] = fma2(w3, zp, d3[p]);
            }
        }
        __syncwarp();   // all lanes done reading z2 before h2 writes

        // ---- layer 2 epilogue: new h2 -> z2 row (32+lane) + gmem trajectory ----
        #pragma unroll
        for (int p = 0; p < PAIRS; p++) {
            u64 hp = lstm_epi(d0[p], d1[p], d2[p], d3[p], c2[p]);
            *(u64*)&z2[(p * 64 + 32 + lane) * 2] = hp;
            float hlo, hhi; upk(hp, hlo, hhi);
            size_t s0 = (size_t)(sWarp + 2 * p);
            h2buf[(s0 * Tt + t) * HID + lane]       = hlo;   // coalesced 128B row
            h2buf[((s0 + 1) * Tt + t) * HID + lane] = hhi;
        }
        __syncwarp();   // h2 visible for next step
    }
}

// ---- head kernel: out[r][o] = h2buf[r] . Wout[o] + bout[o], r = s*Tt + t ----
#define K2_BLOCKS ((Bsz * Tt) / (8 * 32))    // 8 warps/block, 32 rows/warp -> 8192
__global__ void __launch_bounds__(256)
head_kernel(const float* __restrict__ Wout, const float* __restrict__ bout,
            float* __restrict__ out)
{
    __shared__ float swW[FOUT * HID];
    __shared__ float swb[FOUT];
    const int tid = threadIdx.x;
    for (int i = tid; i < FOUT * HID; i += 256) swW[i] = Wout[i];
    for (int i = tid; i < FOUT; i += 256) swb[i] = bout[i];
    __syncthreads();

    const int w    = tid >> 5;
    const int lane = tid & 31;
    const size_t r = ((size_t)blockIdx.x * 8 + w) * 32 + lane;   // one row per lane

    // load h row (32 floats) into registers as 16 f32x2 pairs
    u64 hreg[16];
    const ulonglong2* hp = (const ulonglong2*)(h2buf + r * HID);
    #pragma unroll
    for (int i = 0; i < 8; i++) {
        ulonglong2 v = hp[i];
        hreg[2 * i] = v.x; hreg[2 * i + 1] = v.y;
    }

    float* orow = out + r * FOUT;
    #pragma unroll
    for (int o = 0; o < FOUT; o++) {
        u64 acc = pk(swb[o], 0.f);
        #pragma unroll
        for (int u = 0; u < 16; u++) {
            u64 wp = *(const u64*)&swW[o * HID + 2 * u];   // broadcast LDS.64
            acc = fma2(wp, hreg[u], acc);
        }
        float lo, hi; upk(acc, lo, hi);
        orow[o] = lo + hi;
    }
}

extern "C" void kernel_launch(void* const* d_in, const int* in_sizes, int n_in,
                              void* d_out, int out_size) {
    const float* x    = (const float*)d_in[0];
    const float* Wih1 = (const float*)d_in[1];
    const float* Whh1 = (const float*)d_in[2];
    const float* bih1 = (const float*)d_in[3];
    const float* bhh1 = (const float*)d_in[4];
    const float* Wih2 = (const float*)d_in[5];
    const float* Whh2 = (const float*)d_in[6];
    const float* bih2 = (const float*)d_in[7];
    const float* bhh2 = (const float*)d_in[8];
    const float* Wout = (const float*)d_in[9];
    const float* bout = (const float*)d_in[10];
    float* out = (float*)d_out;

    cudaFuncSetAttribute(lstm_seq_kernel,
                         cudaFuncAttributeMaxDynamicSharedMemorySize, SMEM_BYTES);
    lstm_seq_kernel<<<NBLK, WARPS * 32, SMEM_BYTES>>>(
        x, Wih1, Whh1, bih1, bhh1, Wih2, Whh2, bih2, bhh2, Wout, bout);
    head_kernel<<<K2_BLOCKS, 256>>>(Wout, bout, out);
}